// round 3
// baseline (speedup 1.0000x reference)
#include <cuda_runtime.h>
#include <math.h>

// Problem shapes (fixed by the dataset)
#define N_SRC 8
#define B 4
#define T 2048
#define H 2048
#define THREADS 512          // H/4 floats per thread
#define ROWS 4               // t-rows per CTA (smem prefetch pipeline)
#define EPS 1e-6f
#define RED_PITCH 25         // 24 reduce slots + pad (gcd(25,32)=1 -> conflict-free cols)

// dynamic smem layout: stage[N_SRC][H] floats | red[16][RED_PITCH] | cb_s[8]
#define SMEM_FLOATS (N_SRC * H + 16 * RED_PITCH + 8)

__device__ __forceinline__ unsigned smem_u32(const void* p) {
    return (unsigned)__cvta_generic_to_shared(p);
}
__device__ __forceinline__ void cp_async16(unsigned s, const void* g) {
    asm volatile("cp.async.cg.shared.global [%0], [%1], 16;\n" :: "r"(s), "l"(g));
}
__device__ __forceinline__ void cp_commit() {
    asm volatile("cp.async.commit_group;\n");
}
__device__ __forceinline__ void cp_wait0() {
    asm volatile("cp.async.wait_group 0;\n" ::: "memory");
}

extern __shared__ float dsm[];

__global__ __launch_bounds__(THREADS, 2)
void router_kernel(const float* __restrict__ values,
                   const float* __restrict__ wq,
                   const float* __restrict__ bias,
                   const int* __restrict__ pos_ptr,
                   float* __restrict__ out_routed,   // [B][T][H]
                   float* __restrict__ out_alpha) {  // [B][T][N_SRC]
    const int t0   = blockIdx.x * ROWS;
    const int b    = blockIdx.y;
    const int tid  = threadIdx.x;
    const int warp = tid >> 5, lane = tid & 31;
    const int pos  = pos_ptr ? *pos_ptr : N_SRC;
    const int j    = tid << 2;                      // float index within row

    float* stage = dsm;                             // [N_SRC][H]
    float* red   = dsm + N_SRC * H;                 // [16][RED_PITCH]
    float* cb_s  = red + 16 * RED_PITCH;            // [8]

    const float4 q = *(const float4*)(wq + (size_t)pos * H + j);
    const size_t nstr = (size_t)B * T * H;          // n stride in values
    const size_t base = ((size_t)b * T + t0) * (size_t)H + j;

    const unsigned s_dst = smem_u32(stage) + (unsigned)tid * 16u;

    // prefetch row 0 into smem (async, L1-bypass)
    #pragma unroll
    for (int n = 0; n < N_SRC; n++)
        cp_async16(s_dst + (unsigned)n * (H * 4), values + base + (size_t)n * nstr);
    cp_commit();

    const float inv_sqrt_h = rsqrtf((float)H);
    const float inv_h = 1.0f / (float)H;

    #pragma unroll
    for (int i = 0; i < ROWS; i++) {
        cp_wait0();
        __syncthreads();                            // stage[i] fully resident

        // copy row into registers (conflict-free LDS.128)
        float4 v[N_SRC];
        #pragma unroll
        for (int n = 0; n < N_SRC; n++)
            v[n] = *(const float4*)(stage + n * H + j);
        __syncthreads();                            // all threads done reading stage

        // issue next row's prefetch NOW -> in flight through the whole tail
        if (i + 1 < ROWS) {
            const size_t nb = base + (size_t)(i + 1) * H;
            #pragma unroll
            for (int n = 0; n < N_SRC; n++)
                cp_async16(s_dst + (unsigned)n * (H * 4), values + nb + (size_t)n * nstr);
            cp_commit();
        }

        // per-thread partials
        float ss[N_SRC], dq[N_SRC];
        #pragma unroll
        for (int n = 0; n < N_SRC; n++) {
            const float4 x = v[n];
            ss[n] = x.x*x.x + x.y*x.y + x.z*x.z + x.w*x.w;
            dq[n] = q.x*x.x + q.y*x.y + q.z*x.z + q.w*x.w;
        }

        // row 0 only: cbias_n = q . bias_n partials (folded into same reduction)
        float cb[N_SRC];
        if (i == 0) {
            #pragma unroll
            for (int n = 0; n < N_SRC; n++) {
                const float4 bv = *(const float4*)(bias + (size_t)n * H + j);
                cb[n] = q.x*bv.x + q.y*bv.y + q.z*bv.z + q.w*bv.w;
            }
        }

        // warp butterfly allreduce
        #pragma unroll
        for (int n = 0; n < N_SRC; n++) {
            #pragma unroll
            for (int o = 16; o; o >>= 1) {
                ss[n] += __shfl_xor_sync(0xffffffffu, ss[n], o);
                dq[n] += __shfl_xor_sync(0xffffffffu, dq[n], o);
            }
        }
        if (i == 0) {
            #pragma unroll
            for (int n = 0; n < N_SRC; n++)
                #pragma unroll
                for (int o = 16; o; o >>= 1)
                    cb[n] += __shfl_xor_sync(0xffffffffu, cb[n], o);
        }

        // one write per warp (static register indices)
        if (lane == 0) {
            #pragma unroll
            for (int n = 0; n < N_SRC; n++) {
                red[warp * RED_PITCH + n]     = ss[n];
                red[warp * RED_PITCH + 8 + n] = dq[n];
            }
            if (i == 0) {
                #pragma unroll
                for (int n = 0; n < N_SRC; n++)
                    red[warp * RED_PITCH + 16 + n] = cb[n];
            }
        }
        __syncthreads();                            // single reduce barrier

        // each warp redundantly column-sums (no second barrier)
        const int ncols = (i == 0) ? 24 : 16;
        float tk = 0.f;
        if (lane < ncols) {
            #pragma unroll
            for (int w = 0; w < 16; w++)
                tk += red[w * RED_PITCH + lane];
        }
        if (i == 0 && warp == 0 && lane >= 16 && lane < 24)
            cb_s[lane - 16] = tk;                   // persist cbias for rows 1..3

        // gather totals via shuffle, per-thread softmax over 8 scalars
        float alpha[N_SRC];
        {
            float sc[N_SRC];
            float m = -1e30f;
            #pragma unroll
            for (int n = 0; n < N_SRC; n++) {
                const float sumsq = __shfl_sync(0xffffffffu, tk, n);
                const float dotq  = __shfl_sync(0xffffffffu, tk, 8 + n);
                const float cbn   = (i == 0) ? __shfl_sync(0xffffffffu, tk, 16 + n)
                                             : cb_s[n];
                const float inv = rsqrtf(sumsq * inv_h + EPS);
                sc[n] = (dotq * inv + cbn) * inv_sqrt_h;
                m = fmaxf(m, sc[n]);
            }
            float sum = 0.f;
            #pragma unroll
            for (int n = 0; n < N_SRC; n++) { sc[n] = __expf(sc[n] - m); sum += sc[n]; }
            const float r = 1.0f / sum;
            #pragma unroll
            for (int n = 0; n < N_SRC; n++) alpha[n] = sc[n] * r;
        }

        // routed = sum_n alpha_n * v_n (register-resident), streaming store
        float4 o;
        o.x = alpha[0]*v[0].x; o.y = alpha[0]*v[0].y;
        o.z = alpha[0]*v[0].z; o.w = alpha[0]*v[0].w;
        #pragma unroll
        for (int n = 1; n < N_SRC; n++) {
            o.x += alpha[n]*v[n].x;
            o.y += alpha[n]*v[n].y;
            o.z += alpha[n]*v[n].z;
            o.w += alpha[n]*v[n].w;
        }
        __stcs((float4*)(out_routed + base + (size_t)i * H), o);

        if (tid < N_SRC)
            out_alpha[((size_t)b * T + t0 + i) * N_SRC + tid] = alpha[tid];
    }
}

// ---------------------------------------------------------------------------
// kernel_launch
// inputs: [0] values f32 [8,4,2048,2048], [1] w_query f32 [12,2048],
//         [2] key_pos_bias f32 [12,2048], [3] position i32 scalar
// output: routed f32 [4,2048,2048] followed by alpha f32 [4,2048,8]
// ---------------------------------------------------------------------------
extern "C" void kernel_launch(void* const* d_in, const int* in_sizes, int n_in,
                              void* d_out, int out_size) {
    const float* values = (const float*)d_in[0];
    const float* wq     = (const float*)d_in[1];
    const float* bias   = (const float*)d_in[2];
    const int*   pos    = (n_in > 3) ? (const int*)d_in[3] : nullptr;

    float* out_routed = (float*)d_out;
    float* out_alpha  = (float*)d_out + (size_t)B * T * H;

    const int smem_bytes = SMEM_FLOATS * (int)sizeof(float);
    cudaFuncSetAttribute(router_kernel,
                         cudaFuncAttributeMaxDynamicSharedMemorySize, smem_bytes);

    dim3 grid(T / ROWS, B);
    router_kernel<<<grid, THREADS, smem_bytes>>>(values, wq, bias, pos,
                                                 out_routed, out_alpha);
}

// round 4
// speedup vs baseline: 1.3415x; 1.3415x over previous
#include <cuda_runtime.h>
#include <math.h>

// Problem shapes (fixed by the dataset)
#define N_SRC 8
#define B 4
#define T 2048
#define H 2048
#define THREADS 512          // H/4 floats per thread
#define ROWS 4               // t-rows per CTA (L2-prefetch pipeline)
#define EPS 1e-6f
#define PITCH 16

// Per-n constant: (w_query[pos] . key_pos_bias[n]) / sqrt(H)
__device__ float g_cbias[N_SRC];

// ---------------------------------------------------------------------------
// Prelude: g_cbias[n] = dot(q, bias_n) / sqrt(H)
// ---------------------------------------------------------------------------
__global__ void cbias_kernel(const float* __restrict__ wq,
                             const float* __restrict__ bias,
                             const int* __restrict__ pos_ptr) {
    const int n = blockIdx.x;
    const int pos = pos_ptr ? *pos_ptr : N_SRC;
    const float* q  = wq   + (size_t)pos * H;
    const float* bn = bias + (size_t)n   * H;

    float s = 0.f;
    for (int i = threadIdx.x; i < H; i += blockDim.x)
        s += q[i] * bn[i];

    #pragma unroll
    for (int o = 16; o; o >>= 1) s += __shfl_xor_sync(0xffffffffu, s, o);

    __shared__ float sm[32];
    if ((threadIdx.x & 31) == 0) sm[threadIdx.x >> 5] = s;
    __syncthreads();
    if (threadIdx.x < 32) {
        const int nw = blockDim.x >> 5;
        float v = (threadIdx.x < nw) ? sm[threadIdx.x] : 0.f;
        #pragma unroll
        for (int o = 16; o; o >>= 1) v += __shfl_xor_sync(0xffffffffu, v, o);
        if (threadIdx.x == 0) g_cbias[n] = v * rsqrtf((float)H);
    }
}

__device__ __forceinline__ void prefetch_l2(const void* p) {
    asm volatile("prefetch.global.L2 [%0];" :: "l"(p));
}

// ---------------------------------------------------------------------------
// Main kernel: one CTA per 4 consecutive (b,t) rows.
//  - 8 rows of values in registers (float4/thread per n), front-batched LDG
//  - L2 prefetch of row i+1 issued before row i's reduce tail
//  - fold-reduce (16 SHFL/thread) + single barrier w/ double-buffered red[]
// ---------------------------------------------------------------------------
__global__ __launch_bounds__(THREADS, 2)
void router_kernel(const float* __restrict__ values,
                   const float* __restrict__ wq,
                   const int* __restrict__ pos_ptr,
                   float* __restrict__ out_routed,   // [B][T][H]
                   float* __restrict__ out_alpha) {  // [B][T][N_SRC]
    const int t0   = blockIdx.x * ROWS;
    const int b    = blockIdx.y;
    const int tid  = threadIdx.x;
    const int warp = tid >> 5, lane = tid & 31;
    const int pos  = pos_ptr ? *pos_ptr : N_SRC;
    const int j    = tid << 2;                      // float index within row

    __shared__ float red[2][16 * PITCH];            // double-buffered per-warp totals
    __shared__ float cb_s[N_SRC];

    if (tid < N_SRC) cb_s[tid] = g_cbias[tid];      // ordered by row-0's barrier

    const float4 q = *(const float4*)(wq + (size_t)pos * H + j);
    const size_t nstr     = (size_t)B * T * H;      // n stride in values
    const size_t rowstart = ((size_t)b * T + t0) * (size_t)H;

    // prefetch mapping: thread tid covers line (n = tid>>6, 32-float offset)
    const int pf_n   = tid >> 6;
    const int pf_off = (tid & 63) << 5;             // *32 floats = 128B line

    const float inv_sqrt_h = rsqrtf((float)H);
    const float inv_h = 1.0f / (float)H;

    #pragma unroll
    for (int i = 0; i < ROWS; i++) {
        const size_t rbase = rowstart + (size_t)i * H;

        // front-batched loads of this row (8 x LDG.128)
        float4 v[N_SRC];
        #pragma unroll
        for (int n = 0; n < N_SRC; n++)
            v[n] = __ldcs((const float4*)(values + rbase + (size_t)n * nstr + j));

        // prefetch next row into L2 (keeps DRAM busy through the tail)
        if (i + 1 < ROWS)
            prefetch_l2(values + rbase + H + (size_t)pf_n * nstr + pf_off);

        // per-thread partials: val[0..7] = sum(v^2), val[8..15] = q.v
        float val[16];
        #pragma unroll
        for (int n = 0; n < N_SRC; n++) {
            const float4 x = v[n];
            val[n]     = x.x*x.x + x.y*x.y + x.z*x.z + x.w*x.w;
            val[8 + n] = q.x*x.x + q.y*x.y + q.z*x.z + q.w*x.w;
        }

        // fold-reduce: halve value count each level (16 SHFL total)
        {   // o=16: keep 8
            const bool bit = (lane & 16) != 0;
            #pragma unroll
            for (int k = 0; k < 8; k++) {
                const float send = bit ? val[k] : val[8 + k];
                const float recv = __shfl_xor_sync(0xffffffffu, send, 16);
                val[k] = (bit ? val[8 + k] : val[k]) + recv;
            }
        }
        {   // o=8: keep 4
            const bool bit = (lane & 8) != 0;
            #pragma unroll
            for (int k = 0; k < 4; k++) {
                const float send = bit ? val[k] : val[4 + k];
                const float recv = __shfl_xor_sync(0xffffffffu, send, 8);
                val[k] = (bit ? val[4 + k] : val[k]) + recv;
            }
        }
        {   // o=4: keep 2
            const bool bit = (lane & 4) != 0;
            #pragma unroll
            for (int k = 0; k < 2; k++) {
                const float send = bit ? val[k] : val[2 + k];
                const float recv = __shfl_xor_sync(0xffffffffu, send, 4);
                val[k] = (bit ? val[2 + k] : val[k]) + recv;
            }
        }
        float t;
        {   // o=2: keep 1
            const bool bit = (lane & 2) != 0;
            const float send = bit ? val[0] : val[1];
            const float recv = __shfl_xor_sync(0xffffffffu, send, 2);
            t = (bit ? val[1] : val[0]) + recv;
        }
        t += __shfl_xor_sync(0xffffffffu, t, 1);
        // lane L now holds warp total of value index (L>>1)

        float* rb = red[i & 1];
        if ((lane & 1) == 0)
            rb[warp * PITCH + (lane >> 1)] = t;
        __syncthreads();                            // the only barrier per row

        // every warp redundantly sums the 16 columns
        float tk = 0.f;
        if (lane < 16) {
            #pragma unroll
            for (int w = 0; w < 16; w++)
                tk += rb[w * PITCH + lane];
        }

        // per-thread softmax over 8 scalars (gather via shuffle)
        float alpha[N_SRC];
        {
            float sc[N_SRC];
            float m = -1e30f;
            #pragma unroll
            for (int n = 0; n < N_SRC; n++) {
                const float sumsq = __shfl_sync(0xffffffffu, tk, n);
                const float dotq  = __shfl_sync(0xffffffffu, tk, 8 + n);
                const float inv   = rsqrtf(sumsq * inv_h + EPS);
                sc[n] = dotq * inv * inv_sqrt_h + cb_s[n];
                m = fmaxf(m, sc[n]);
            }
            float sum = 0.f;
            #pragma unroll
            for (int n = 0; n < N_SRC; n++) { sc[n] = __expf(sc[n] - m); sum += sc[n]; }
            const float r = 1.0f / sum;
            #pragma unroll
            for (int n = 0; n < N_SRC; n++) alpha[n] = sc[n] * r;
        }

        // routed = sum_n alpha_n * v_n  (register-resident), streaming store
        float4 o;
        o.x = alpha[0]*v[0].x; o.y = alpha[0]*v[0].y;
        o.z = alpha[0]*v[0].z; o.w = alpha[0]*v[0].w;
        #pragma unroll
        for (int n = 1; n < N_SRC; n++) {
            o.x += alpha[n]*v[n].x;
            o.y += alpha[n]*v[n].y;
            o.z += alpha[n]*v[n].z;
            o.w += alpha[n]*v[n].w;
        }
        __stcs((float4*)(out_routed + rbase + j), o);

        if (tid < N_SRC)
            out_alpha[((size_t)b * T + t0 + i) * N_SRC + tid] = alpha[tid];
    }
}

// ---------------------------------------------------------------------------
// kernel_launch
// inputs: [0] values f32 [8,4,2048,2048], [1] w_query f32 [12,2048],
//         [2] key_pos_bias f32 [12,2048], [3] position i32 scalar
// output: routed f32 [4,2048,2048] followed by alpha f32 [4,2048,8]
// ---------------------------------------------------------------------------
extern "C" void kernel_launch(void* const* d_in, const int* in_sizes, int n_in,
                              void* d_out, int out_size) {
    const float* values = (const float*)d_in[0];
    const float* wq     = (const float*)d_in[1];
    const float* bias   = (const float*)d_in[2];
    const int*   pos    = (n_in > 3) ? (const int*)d_in[3] : nullptr;

    float* out_routed = (float*)d_out;
    float* out_alpha  = (float*)d_out + (size_t)B * T * H;

    cbias_kernel<<<N_SRC, 256>>>(wq, bias, pos);

    dim3 grid(T / ROWS, B);
    router_kernel<<<grid, THREADS>>>(values, wq, pos, out_routed, out_alpha);
}